// round 2
// baseline (speedup 1.0000x reference)
#include <cuda_runtime.h>
#include <cuda_bf16.h>
#include <cstdint>

// Shapes (fixed by the problem)
#define NB 32      // N
#define KB 32      // K
#define TB 128     // T
#define HB 768     // H
#define H2 1536    // 2H

// Output layout (float32, outputs flattened + concatenated in return order):
//   score          [0, 1024)
//   shifted_encoded[1024, 1024+3145728)
//   shifted_mask   [3146752, +4096)
//   shifted_use    [3150848, +24576)
//   shifted_index  [3175424, +4096)
#define OFF_SCORE   0
#define OFF_ENC     1024
#define OFF_MASK    3146752
#define OFF_USE     3150848
#define OFF_IDX     3175424

// Scratch (device globals — no allocation allowed)
__device__ float g_cqk_pro[NB * HB];
__device__ float g_u[NB * HB];

// ---------------------------------------------------------------------------
// Kernel A: cqk_pro[n,h] = sum_j cqk[n,j] * W_cqk[h,j] + b_cqk[h]
//   cqk[n,j] = j<768 ? ctx1[n,2,j] : tku[n,j-768]
// Tiled GEMM: M=32, N=768 (h), K=1536 (j). Block: 64 h x 32 n, 256 threads.
// ---------------------------------------------------------------------------
__global__ void kA_cqkpro(const float* __restrict__ ctx1,
                          const float* __restrict__ tku,
                          const float* __restrict__ Wcqk,
                          const float* __restrict__ bcqk,
                          float* __restrict__ outp)
{
    __shared__ float As[NB][64];       // 8 KB
    __shared__ float Bs[64][65];       // ~16.6 KB, padded vs conflicts

    const int h0  = blockIdx.x * 64;
    const int tid = threadIdx.x;
    const int tx  = tid & 63;          // h within tile
    const int tyg = tid >> 6;          // n-group (4 groups of 8 rows)

    float acc[8];
#pragma unroll
    for (int i = 0; i < 8; i++) acc[i] = 0.f;

    for (int j0 = 0; j0 < H2; j0 += 64) {
        // load A tile (32 x 64), coalesced along j
        for (int i = tid; i < NB * 64; i += 256) {
            int n = i >> 6, kk = i & 63;
            int j = j0 + kk;
            float v = (j < HB) ? ctx1[n * 3 * HB + 2 * HB + j]
                               : tku[n * HB + (j - HB)];
            As[n][kk] = v;
        }
        // load B tile: Bs[kk][hh] = Wcqk[(h0+hh)*1536 + j0+kk], coalesced along kk
        for (int i = tid; i < 64 * 64; i += 256) {
            int hh = i >> 6, kk = i & 63;
            Bs[kk][hh] = Wcqk[(size_t)(h0 + hh) * H2 + j0 + kk];
        }
        __syncthreads();
#pragma unroll 8
        for (int kk = 0; kk < 64; kk++) {
            float bv = Bs[kk][tx];
#pragma unroll
            for (int i = 0; i < 8; i++)
                acc[i] += As[tyg * 8 + i][kk] * bv;
        }
        __syncthreads();
    }
    float bb = bcqk[h0 + tx];
#pragma unroll
    for (int i = 0; i < 8; i++)
        outp[(size_t)(tyg * 8 + i) * HB + h0 + tx] = acc[i] + bb;
}

// ---------------------------------------------------------------------------
// Kernel B: u[n,h] = sum_g cqk_pro[n,g] * W_k[g,h]
// Tiled GEMM: M=32, N=768, K=768.
// ---------------------------------------------------------------------------
__global__ void kB_u(const float* __restrict__ cqkp,
                     const float* __restrict__ Wk,
                     float* __restrict__ outp)
{
    __shared__ float As[NB][64];
    __shared__ float Bs[64][65];

    const int h0  = blockIdx.x * 64;
    const int tid = threadIdx.x;
    const int tx  = tid & 63;
    const int tyg = tid >> 6;

    float acc[8];
#pragma unroll
    for (int i = 0; i < 8; i++) acc[i] = 0.f;

    for (int j0 = 0; j0 < HB; j0 += 64) {
        for (int i = tid; i < NB * 64; i += 256) {
            int n = i >> 6, kk = i & 63;
            As[n][kk] = cqkp[(size_t)n * HB + j0 + kk];
        }
        // Bs[kk][hh] = Wk[(j0+kk)*768 + h0+hh], coalesced along hh
        for (int i = tid; i < 64 * 64; i += 256) {
            int kk = i >> 6, hh = i & 63;
            Bs[kk][hh] = Wk[(size_t)(j0 + kk) * HB + h0 + hh];
        }
        __syncthreads();
#pragma unroll 8
        for (int kk = 0; kk < 64; kk++) {
            float bv = Bs[kk][tx];
#pragma unroll
            for (int i = 0; i < 8; i++)
                acc[i] += As[tyg * 8 + i][kk] * bv;
        }
        __syncthreads();
    }
#pragma unroll
    for (int i = 0; i < 8; i++)
        outp[(size_t)(tyg * 8 + i) * HB + h0 + tx] = acc[i];
}

// ---------------------------------------------------------------------------
// Kernel C: score[n,k] = ck_mask ? pe1[n,k,:].u[n,:] + b_k.cqk_pro[n,:] : -1e20
// One block per n; 8 warps, each handles 4 k values. u[n] cached in smem.
// ck_mask read as 4-byte elements (nonzero test covers int32 and float32).
// ---------------------------------------------------------------------------
__global__ void kC_score(const float* __restrict__ pe1,
                         const int* __restrict__ ckm,
                         const float* __restrict__ u_,
                         const float* __restrict__ cqkp,
                         const float* __restrict__ bk,
                         float* __restrict__ out)
{
    const int n   = blockIdx.x;
    const int tid = threadIdx.x;      // 256
    const int lane = tid & 31;
    const int wid  = tid >> 5;

    __shared__ __align__(16) float su[HB];
    __shared__ float red[8];

    float cpart = 0.f;
    for (int h = tid; h < HB; h += 256) {
        float uv = u_[(size_t)n * HB + h];
        su[h] = uv;
        cpart += bk[h] * cqkp[(size_t)n * HB + h];
    }
#pragma unroll
    for (int o = 16; o; o >>= 1) cpart += __shfl_xor_sync(0xFFFFFFFFu, cpart, o);
    if (lane == 0) red[wid] = cpart;
    __syncthreads();
    float c_n = 0.f;
#pragma unroll
    for (int i = 0; i < 8; i++) c_n += red[i];

    const float4* uu = (const float4*)su;
    for (int k = wid; k < KB; k += 8) {
        const float4* p = (const float4*)(pe1 + ((size_t)n * KB + k) * HB);
        float acc = 0.f;
#pragma unroll 2
        for (int i = lane; i < HB / 4; i += 32) {
            float4 a = p[i];
            float4 b = uu[i];
            acc += a.x * b.x + a.y * b.y + a.z * b.z + a.w * b.w;
        }
#pragma unroll
        for (int o = 16; o; o >>= 1) acc += __shfl_xor_sync(0xFFFFFFFFu, acc, o);
        if (lane == 0)
            out[OFF_SCORE + n * KB + k] = (ckm[n * KB + k] != 0) ? (acc + c_n) : -1e20f;
    }
}

// ---------------------------------------------------------------------------
// Kernel D: shifted_encoded = pool_encoded_0[n, label[n]]  (12 MB copy, float4)
// grid (96, 32), block 256 -> exactly one float4 per thread per n.
// ---------------------------------------------------------------------------
__global__ void kD_gather_enc(const float* __restrict__ pe0,
                              const int* __restrict__ label,
                              float* __restrict__ out)
{
    const int n = blockIdx.y;
    const int lab = label[n];
    const size_t src_base = ((size_t)n * KB + lab) * (size_t)TB * HB;
    const float4* src = (const float4*)(pe0 + src_base);
    float4* dst = (float4*)(out + OFF_ENC + (size_t)n * TB * HB);

    const int idx = blockIdx.x * blockDim.x + threadIdx.x;  // 0..24575
    dst[idx] = src[idx];
}

// ---------------------------------------------------------------------------
// Kernel E: small gathers (mask -> float, use copy, tokens -> float)
// pool_mask read as 4-byte elements (nonzero covers int32 and float32).
// ---------------------------------------------------------------------------
__global__ void kE_gather_small(const int* __restrict__ pm,
                                const float* __restrict__ pe1,
                                const int* __restrict__ pt,
                                const int* __restrict__ label,
                                float* __restrict__ out)
{
    const int n = blockIdx.x;
    const int lab = label[n];
    const int base_mk = (n * KB + lab) * TB;

    for (int t = threadIdx.x; t < TB; t += blockDim.x) {
        out[OFF_MASK + n * TB + t] = (pm[base_mk + t] != 0) ? 1.f : 0.f;
        out[OFF_IDX  + n * TB + t] = (float)pt[base_mk + t];
    }
    const size_t use_base = ((size_t)n * KB + lab) * HB;
    for (int h = threadIdx.x; h < HB; h += blockDim.x)
        out[OFF_USE + n * HB + h] = pe1[use_base + h];
}

// ---------------------------------------------------------------------------
extern "C" void kernel_launch(void* const* d_in, const int* in_sizes, int n_in,
                              void* d_out, int out_size)
{
    const float* ctx1 = (const float*)d_in[0];         // (32,3,768)
    const float* tku  = (const float*)d_in[1];         // (32,768)
    const float* pe0  = (const float*)d_in[2];         // (32,32,128,768)
    const float* pe1  = (const float*)d_in[3];         // (32,32,768)
    const int*   pm   = (const int*)d_in[4];           // (32,32,128) bool->4B
    const int*   ckm  = (const int*)d_in[5];           // (32,32) bool->4B
    const int*   lab  = (const int*)d_in[6];           // (32,)
    const int*   pt   = (const int*)d_in[7];           // (32,32,128) int32
    const float* Wcqk = (const float*)d_in[8];         // (768,1536)
    const float* bcqk = (const float*)d_in[9];         // (768,)
    const float* Wk   = (const float*)d_in[10];        // (768,768)
    const float* bk   = (const float*)d_in[11];        // (768,)

    float* out = (float*)d_out;

    float* d_cqkp;  cudaGetSymbolAddress((void**)&d_cqkp, g_cqk_pro);
    float* d_u;     cudaGetSymbolAddress((void**)&d_u, g_u);

    // Independent of the GEMM chain: big gather + small gathers first
    kD_gather_enc<<<dim3(96, NB), 256>>>(pe0, lab, out);
    kE_gather_small<<<NB, 256>>>(pm, pe1, pt, lab, out);

    // GEMM chain
    kA_cqkpro<<<HB / 64, 256>>>(ctx1, tku, Wcqk, bcqk, d_cqkp);
    kB_u<<<HB / 64, 256>>>(d_cqkp, Wk, d_u);
    kC_score<<<NB, 256>>>(pe1, ckm, d_u, d_cqkp, bk, out);
}

// round 3
// speedup vs baseline: 4.2777x; 4.2777x over previous
#include <cuda_runtime.h>
#include <cstdint>

#define NB 32
#define KB 32
#define TB 128
#define HB 768
#define H2 1536

// Output layout (float32, concat of flattened outputs)
#define OFF_SCORE   0
#define OFF_ENC     1024
#define OFF_MASK    3146752
#define OFF_USE     3150848
#define OFF_IDX     3175424

__device__ float g_cqk_pro[NB * HB];
__device__ float g_u[NB * HB];
__device__ float g_c[NB];

// ---------------------------------------------------------------------------
// Kernel 1 (fused, 3872 blocks x 256):
//   blocks [0,768):     kA  cqk_pro[n,h] = cqk[n,:] . W_cqk[h,:] + b_cqk[h]
//                       one warp -> 4 outputs (same n), float4 dots over K=1536
//   blocks [768,3840):  big gather shifted_encoded (12 MB, one float4/thread)
//   blocks [3840,3872): small gathers (mask, tokens, use)
// ---------------------------------------------------------------------------
__global__ void __launch_bounds__(256) k1_fused(
    const float* __restrict__ ctx1,
    const float* __restrict__ tku,
    const float* __restrict__ Wcqk,
    const float* __restrict__ bcqk,
    const float* __restrict__ pe0,
    const float* __restrict__ pe1,
    const int*   __restrict__ pm,
    const int*   __restrict__ pt,
    const int*   __restrict__ label,
    float* __restrict__ cqkp,
    float* __restrict__ out)
{
    const int b   = blockIdx.x;
    const int tid = threadIdx.x;

    if (b < 768) {
        const int wid  = tid >> 5;
        const int lane = tid & 31;
        const int gw   = b * 8 + wid;          // 0..6143
        const int n    = gw / 192;             // 192 warp-groups per n
        const int h0   = (gw % 192) * 4;

        // A row (cqk[n,:]) : j = i*128 + lane*4, 12 float4 per lane
        float4 a[12];
        const float4* arow0 = (const float4*)(ctx1 + (size_t)n * 3 * HB + 2 * HB);
        const float4* arow1 = (const float4*)(tku  + (size_t)n * HB);
#pragma unroll
        for (int i = 0; i < 6; i++) a[i]     = arow0[i * 32 + lane];
#pragma unroll
        for (int i = 0; i < 6; i++) a[i + 6] = arow1[i * 32 + lane];

        float acc[4];
#pragma unroll
        for (int hh = 0; hh < 4; hh++) {
            const float4* w = (const float4*)(Wcqk + (size_t)(h0 + hh) * H2);
            float s = 0.f;
#pragma unroll
            for (int i = 0; i < 12; i++) {
                float4 wv = w[i * 32 + lane];
                s += a[i].x * wv.x + a[i].y * wv.y + a[i].z * wv.z + a[i].w * wv.w;
            }
            acc[hh] = s;
        }
#pragma unroll
        for (int hh = 0; hh < 4; hh++) {
#pragma unroll
            for (int o = 16; o; o >>= 1)
                acc[hh] += __shfl_xor_sync(0xFFFFFFFFu, acc[hh], o);
        }
        if (lane == 0) {
            float* dst = cqkp + (size_t)n * HB + h0;
            dst[0] = acc[0] + bcqk[h0 + 0];
            dst[1] = acc[1] + bcqk[h0 + 1];
            dst[2] = acc[2] + bcqk[h0 + 2];
            dst[3] = acc[3] + bcqk[h0 + 3];
        }
    } else if (b < 3840) {
        // gather shifted_encoded: 786432 float4 total
        const int flat = (b - 768) * 256 + tid;
        const int n = flat / 24576;            // 24576 float4 per n
        const int i = flat - n * 24576;
        const float4* src = (const float4*)(pe0 + ((size_t)n * KB + label[n]) * (size_t)TB * HB);
        float4* dst = (float4*)(out + OFF_ENC + (size_t)n * TB * HB);
        dst[i] = src[i];
    } else {
        const int n   = b - 3840;
        const int lab = label[n];
        const int base = (n * KB + lab) * TB;
        for (int t = tid; t < TB; t += 256) {
            out[OFF_MASK + n * TB + t] = (pm[base + t] != 0) ? 1.f : 0.f;
            out[OFF_IDX  + n * TB + t] = (float)pt[base + t];
        }
        const size_t ub = ((size_t)n * KB + lab) * HB;
        for (int h = tid; h < HB; h += 256)
            out[OFF_USE + n * HB + h] = pe1[ub + h];
    }
}

// ---------------------------------------------------------------------------
// Kernel 2 (97 blocks x 256):
//   blocks [0,96): u[n,h] = sum_g cqk_pro[n,g] * W_k[g,h]
//     warp -> 32 consecutive h of one n; g-loop with shfl broadcast; Wk rows
//     coalesced across lanes. 4 accumulators break FMA chain.
//   block 96: c[n] = b_k . cqk_pro[n]
// ---------------------------------------------------------------------------
__global__ void __launch_bounds__(256) k2_u(
    const float* __restrict__ cqkp,
    const float* __restrict__ Wk,
    const float* __restrict__ bk,
    float* __restrict__ u_,
    float* __restrict__ c_)
{
    const int b    = blockIdx.x;
    const int tid  = threadIdx.x;
    const int wid  = tid >> 5;
    const int lane = tid & 31;

    if (b < 96) {
        const int gw = b * 8 + wid;            // 0..767
        const int n  = gw / 24;                // 24 warp-tiles of 32 h per n
        const int h  = (gw % 24) * 32 + lane;
        const float* wcol = Wk + h;
        const float* cr   = cqkp + (size_t)n * HB;

        float acc0 = 0.f, acc1 = 0.f, acc2 = 0.f, acc3 = 0.f;
        for (int g0 = 0; g0 < HB; g0 += 32) {
            float cg = cr[g0 + lane];
#pragma unroll
            for (int j = 0; j < 32; j += 4) {
                acc0 += __shfl_sync(0xFFFFFFFFu, cg, j + 0) * wcol[(size_t)(g0 + j + 0) * HB];
                acc1 += __shfl_sync(0xFFFFFFFFu, cg, j + 1) * wcol[(size_t)(g0 + j + 1) * HB];
                acc2 += __shfl_sync(0xFFFFFFFFu, cg, j + 2) * wcol[(size_t)(g0 + j + 2) * HB];
                acc3 += __shfl_sync(0xFFFFFFFFu, cg, j + 3) * wcol[(size_t)(g0 + j + 3) * HB];
            }
        }
        u_[(size_t)n * HB + h] = (acc0 + acc1) + (acc2 + acc3);
    } else {
#pragma unroll
        for (int r = 0; r < 4; r++) {
            const int n = wid + r * 8;
            const float4* cc  = (const float4*)(cqkp + (size_t)n * HB);
            const float4* bb4 = (const float4*)bk;
            float s = 0.f;
#pragma unroll
            for (int i = 0; i < 6; i++) {
                float4 x = cc[i * 32 + lane];
                float4 y = bb4[i * 32 + lane];
                s += x.x * y.x + x.y * y.y + x.z * y.z + x.w * y.w;
            }
#pragma unroll
            for (int o = 16; o; o >>= 1) s += __shfl_xor_sync(0xFFFFFFFFu, s, o);
            if (lane == 0) c_[n] = s;
        }
    }
}

// ---------------------------------------------------------------------------
// Kernel 3 (128 blocks x 256): score[n,k]
//   block -> (n, group of 8 k); warp -> one k; float4 dot over H=768.
// ---------------------------------------------------------------------------
__global__ void __launch_bounds__(256) k3_score(
    const float* __restrict__ pe1,
    const int*   __restrict__ ckm,
    const float* __restrict__ u_,
    const float* __restrict__ c_,
    float* __restrict__ out)
{
    const int n    = blockIdx.x >> 2;
    const int kg   = blockIdx.x & 3;
    const int wid  = threadIdx.x >> 5;
    const int lane = threadIdx.x & 31;
    const int k    = kg * 8 + wid;

    const float4* p  = (const float4*)(pe1 + ((size_t)n * KB + k) * HB);
    const float4* uu = (const float4*)(u_ + (size_t)n * HB);
    float s = 0.f;
#pragma unroll
    for (int i = 0; i < 6; i++) {
        float4 a  = p[i * 32 + lane];
        float4 bq = uu[i * 32 + lane];
        s += a.x * bq.x + a.y * bq.y + a.z * bq.z + a.w * bq.w;
    }
#pragma unroll
    for (int o = 16; o; o >>= 1) s += __shfl_xor_sync(0xFFFFFFFFu, s, o);
    if (lane == 0)
        out[OFF_SCORE + n * KB + k] = (ckm[n * KB + k] != 0) ? (s + c_[n]) : -1e20f;
}

// ---------------------------------------------------------------------------
extern "C" void kernel_launch(void* const* d_in, const int* in_sizes, int n_in,
                              void* d_out, int out_size)
{
    const float* ctx1 = (const float*)d_in[0];
    const float* tku  = (const float*)d_in[1];
    const float* pe0  = (const float*)d_in[2];
    const float* pe1  = (const float*)d_in[3];
    const int*   pm   = (const int*)d_in[4];
    const int*   ckm  = (const int*)d_in[5];
    const int*   lab  = (const int*)d_in[6];
    const int*   pt   = (const int*)d_in[7];
    const float* Wcqk = (const float*)d_in[8];
    const float* bcqk = (const float*)d_in[9];
    const float* Wk   = (const float*)d_in[10];
    const float* bk   = (const float*)d_in[11];

    float* out = (float*)d_out;

    float* d_cqkp; cudaGetSymbolAddress((void**)&d_cqkp, g_cqk_pro);
    float* d_u;    cudaGetSymbolAddress((void**)&d_u,    g_u);
    float* d_c;    cudaGetSymbolAddress((void**)&d_c,    g_c);

    k1_fused<<<3872, 256>>>(ctx1, tku, Wcqk, bcqk, pe0, pe1, pm, pt, lab, d_cqkp, out);
    k2_u<<<97, 256>>>(d_cqkp, Wk, bk, d_u, d_c);
    k3_score<<<128, 256>>>(pe1, ckm, d_u, d_c, out);
}